// round 13
// baseline (speedup 1.0000x reference)
#include <cuda_runtime.h>
#include <cuda_bf16.h>
#include <cstdint>

// Problem constants
#define BATCH 32
#define C     512
#define P     196
#define D     8192
#define DMASK (D - 1)

#define C1B   64           // c1 rows per CTA
#define C2B   32           // c2 chunk (16 chunks, 8 per warp group)
#define NKS   13           // k-steps of 16 (208 padded)
#define NG    26           // 16B hi groups per row
#define SPROW 832          // scratch row bytes: 416 hi + 416 lo
#define LDB   848          // smem row stride; 848/16=53 (odd mod 8) -> conflict-free
#define LOOFF 416          // lo region offset within a row
#define NTHREADS 256
#define BBUF  (C2B * LDB)  // 27136 B per B buffer

#define PREP_BLKS  2048    // S-scan + out-zero blocks
#define SPLIT_BLKS 3328    // bf16-split blocks (2*32*512*26/256)

// Hash/sign tables (orig channel order) + sorted-permutation tables.
__device__ int   g_h1[C];
__device__ int   g_h2[C];
__device__ float g_s1[C];
__device__ float g_s2[C];
__device__ int   g_p1[C],  g_p2[C];    // sorted idx -> orig channel
__device__ int   g_h1s[C], g_h2s[C];   // h sorted ascending
__device__ float g_s1s[C], g_s2s[C];   // s in sorted order

// Precomputed (sign-free) bf16 hi/lo tiles: [2][32 b][512 c][832 B]
__device__ unsigned char g_split[2u * BATCH * C * SPROW];

// ---------------------------------------------------------------------------
// bf16 error-compensated split helpers
// ---------------------------------------------------------------------------
__device__ __forceinline__ void split2(float x0, float x1,
                                       uint32_t& hi, uint32_t& lo) {
    __nv_bfloat16 h0 = __float2bfloat16(x0);
    __nv_bfloat16 h1 = __float2bfloat16(x1);
    __nv_bfloat16 l0 = __float2bfloat16(x0 - __bfloat162float(h0));
    __nv_bfloat16 l1 = __float2bfloat16(x1 - __bfloat162float(h1));
    __nv_bfloat162 hp = __halves2bfloat162(h0, h1);
    __nv_bfloat162 lp = __halves2bfloat162(l0, l1);
    hi = *(uint32_t*)&hp;
    lo = *(uint32_t*)&lp;
}

// ---------------------------------------------------------------------------
// Kernel 1 (merged): S-matrix (h,s) extraction + out-zeroing  ||  bf16 split
// of raw bottom data (sign applied later at scatter).  grid: 5376 x 256
// ---------------------------------------------------------------------------
__global__ void cbp_prep(const float* __restrict__ S1, const float* __restrict__ S2,
                         const float* __restrict__ B1g, const float* __restrict__ B2g,
                         float* __restrict__ out) {
    const int bx = blockIdx.x;
    if (bx < PREP_BLKS) {
        const int row  = bx & 511;
        const int y    = (bx >> 9) & 1;
        const int half = bx >> 10;
        const float4* r = (const float4*)(((y == 0) ? S1 : S2)
                                          + (size_t)row * D + half * (D / 2));
        #pragma unroll
        for (int i = 0; i < (D / 2 / 4) / NTHREADS; i++) {
            int j4 = threadIdx.x + i * NTHREADS;
            float4 v = r[j4];
            float nz = 0.0f; int off = 0;
            if (v.x != 0.0f) { nz = v.x; off = 0; }
            if (v.y != 0.0f) { nz = v.y; off = 1; }
            if (v.z != 0.0f) { nz = v.z; off = 2; }
            if (v.w != 0.0f) { nz = v.w; off = 3; }
            if (nz != 0.0f) {
                int j = half * (D / 2) + j4 * 4 + off;
                if (y == 0) { g_h1[row] = j; g_s1[row] = nz; }
                else        { g_h2[row] = j; g_s2[row] = nz; }
            }
        }
        int flat = bx * NTHREADS + threadIdx.x;
        if (flat < BATCH * D) out[flat] = 0.0f;
    } else {
        int task = (bx - PREP_BLKS) * NTHREADS + threadIdx.x;
        int g   = task % NG;
        int row = task / NG;                  // [inp][b][c] flattened
        int inp = row >> 14;
        int rc  = row & 16383;
        const float* src = (inp ? B2g : B1g) + (size_t)rc * P + 8 * g;
        float4 va = (g <= 24) ? *(const float4*)src
                              : make_float4(0.f, 0.f, 0.f, 0.f);
        float4 vb = (g <= 23) ? *(const float4*)(src + 4)
                              : make_float4(0.f, 0.f, 0.f, 0.f);
        uint4 H, L;
        split2(va.x, va.y, H.x, L.x);
        split2(va.z, va.w, H.y, L.y);
        split2(vb.x, vb.y, H.z, L.z);
        split2(vb.z, vb.w, H.w, L.w);
        unsigned char* dst = g_split + (size_t)row * SPROW;
        *(uint4*)(dst + g * 16) = H;
        *(uint4*)(dst + LOOFF + g * 16) = L;
    }
}

// ---------------------------------------------------------------------------
// Kernel 2: rank-sort channels by hash.  block 0: h1; block 1: h2.
// ---------------------------------------------------------------------------
__global__ void cbp_sort() {
    __shared__ int hh[C];
    const int tid = threadIdx.x;
    int*   h = blockIdx.x ? g_h2  : g_h1;
    float* s = blockIdx.x ? g_s2  : g_s1;
    int*   p = blockIdx.x ? g_p2  : g_p1;
    int*   hs = blockIdx.x ? g_h2s : g_h1s;
    float* ss = blockIdx.x ? g_s2s : g_s1s;
    hh[tid] = h[tid];
    __syncthreads();
    int mine = hh[tid];
    int rank = 0;
    for (int j = 0; j < C; j++) {
        int hj = hh[j];
        rank += (hj < mine) || (hj == mine && j < tid);
    }
    p[rank]  = tid;
    hs[rank] = mine;
    ss[rank] = s[tid];
}

// ---------------------------------------------------------------------------
// MMA / ldmatrix / cp.async helpers
// ---------------------------------------------------------------------------
__device__ __forceinline__ void mma_bf16(float c[4], const uint32_t a[4],
                                         uint32_t b0, uint32_t b1) {
    asm volatile(
        "mma.sync.aligned.m16n8k16.row.col.f32.bf16.bf16.f32 "
        "{%0,%1,%2,%3}, {%4,%5,%6,%7}, {%8,%9}, {%0,%1,%2,%3};"
        : "+f"(c[0]), "+f"(c[1]), "+f"(c[2]), "+f"(c[3])
        : "r"(a[0]), "r"(a[1]), "r"(a[2]), "r"(a[3]), "r"(b0), "r"(b1));
}

__device__ __forceinline__ void ldsm4(uint32_t r[4], uint32_t addr) {
    asm volatile(
        "ldmatrix.sync.aligned.m8n8.x4.shared.b16 {%0,%1,%2,%3}, [%4];"
        : "=r"(r[0]), "=r"(r[1]), "=r"(r[2]), "=r"(r[3]) : "r"(addr));
}

__device__ __forceinline__ void cp16(uint32_t smem_dst, const void* gsrc) {
    asm volatile("cp.async.cg.shared.global [%0], [%1], 16;"
                 :: "r"(smem_dst), "l"(gsrc) : "memory");
}

// ---------------------------------------------------------------------------
// Kernel 3: HMMA bf16 3-split Gram + sorted REDG scatter, with the CTA split
// into TWO independent warp-group pipelines (warps 0-3: chunks 0-7 / buf 0,
// warps 4-7: chunks 8-15 / buf 1), synced by named barriers only.
// grid: (8, 32); smem 54.3K (A) + 2 x 27.1K (B) = 108.5K -> 2 CTAs/SM
// => 4 independent pipelines per SM.
// ---------------------------------------------------------------------------
#define SMEM_BYTES (C1B * LDB + 2 * BBUF)

__global__ void __launch_bounds__(NTHREADS, 2)
cbp_main(float* __restrict__ out) {
    extern __shared__ char smc[];
    char* At = smc;                          // [64][848]: hi | lo

    const int tid  = threadIdx.x;
    const int wid  = tid >> 5;
    const int lane = tid & 31;
    const int g    = lane >> 2;
    const int tg   = lane & 3;
    const int grp  = wid >> 2;               // warp group 0 / 1
    const int gt   = tid & 127;              // thread id within group
    const int wg   = wid & 3;                // warp within group
    const int wm   = wg >> 1;                // 0..1 (32-row half)
    const int wn   = wg & 1;                 // 0..1 (16-col half of 32)
    const int b     = blockIdx.y;
    const int c1blk = blockIdx.x * C1B;      // index in SORTED c1 domain
    const int barid = 1 + grp;

    const uint32_t As = (uint32_t)__cvta_generic_to_shared(At);
    const uint32_t Bs = As + C1B * LDB + grp * BBUF;
    char* Bt = At + C1B * LDB + grp * BBUF;

    // ---- Stage A tile (all 256 threads, 13 x 16B each, rows perm by h1) ----
    {
        const unsigned char* baseA = g_split + (size_t)b * C * SPROW;
        #pragma unroll
        for (int it = 0; it < 13; it++) {
            int idx = tid + it * NTHREADS;    // < 3328 = 64*52
            int row = idx / 52, j = idx % 52;
            int orig = __ldg(g_p1 + c1blk + row);
            cp16(As + row * LDB + j * 16,
                 baseA + (size_t)orig * SPROW + j * 16);
        }
    }

    // ---- Stage this group's first B chunk (128 threads, 13 x 16B each) ----
    const unsigned char* baseB = g_split + ((size_t)BATCH * C + (size_t)b * C) * SPROW;
    int brow[13], bj[13];
    #pragma unroll
    for (int it = 0; it < 13; it++) {
        int idx = gt + it * 128;              // < 1664 = 32*52
        brow[it] = idx / 52;
        bj[it]   = idx % 52;
    }
    const int cc0 = grp * 8;                  // this group's first chunk
    #pragma unroll
    for (int it = 0; it < 13; it++) {
        int orig = __ldg(g_p2 + cc0 * C2B + brow[it]);
        cp16(Bs + brow[it] * LDB + bj[it] * 16,
             baseB + (size_t)orig * SPROW + bj[it] * 16);
    }
    asm volatile("cp.async.commit_group;" ::: "memory");
    asm volatile("cp.async.wait_group 0;" ::: "memory");
    __syncthreads();                          // A + first B visible everywhere

    // ---- ldmatrix per-lane base addresses ----
    const int t  = lane >> 3;
    const int rr = lane & 7;
    const uint32_t aoff = (uint32_t)(wm * 32 + (t & 1) * 8 + rr) * LDB + (t >> 1) * 16;
    const uint32_t boff = (uint32_t)(wn * 16 + (t >> 1) * 8 + rr) * LDB + (t & 1) * 16;
    const uint32_t aHa = As + aoff, aLa = As + aoff + LOOFF;
    const uint32_t bHa = Bs + boff, bLa = Bs + boff + LOOFF;

    // Preload sorted h1 + s1 for this thread's rows
    int   h1r[2][2];
    float s1r[2][2];
    #pragma unroll
    for (int mt = 0; mt < 2; mt++) {
        int r0 = c1blk + wm * 32 + mt * 16 + g;
        h1r[mt][0] = g_h1s[r0];      h1r[mt][1] = g_h1s[r0 + 8];
        s1r[mt][0] = g_s1s[r0];      s1r[mt][1] = g_s1s[r0 + 8];
    }

    float* outb = out + (size_t)b * D;

    for (int i = 0; i < 8; i++) {
        const int cc = cc0 + i;

        // ---- 64x32 group tile: warp 32x16, ldmatrix + mma, 3-split ----
        float cfr[2][2][4];
        #pragma unroll
        for (int mt = 0; mt < 2; mt++)
            #pragma unroll
            for (int nt = 0; nt < 2; nt++)
                #pragma unroll
                for (int q = 0; q < 4; q++) cfr[mt][nt][q] = 0.0f;

        #pragma unroll
        for (int ks = 0; ks < NKS; ks++) {
            const uint32_t kb = ks * 32;
            uint32_t ah[2][4], al[2][4], bh[4], bl[4];
            ldsm4(ah[0], aHa + kb);
            ldsm4(ah[1], aHa + 16 * LDB + kb);
            ldsm4(al[0], aLa + kb);
            ldsm4(al[1], aLa + 16 * LDB + kb);
            ldsm4(bh, bHa + kb);
            ldsm4(bl, bLa + kb);
            #pragma unroll
            for (int mt = 0; mt < 2; mt++)
                #pragma unroll
                for (int nt = 0; nt < 2; nt++) {
                    mma_bf16(cfr[mt][nt], ah[mt], bh[2 * nt], bh[2 * nt + 1]); // hi*hi
                    mma_bf16(cfr[mt][nt], ah[mt], bl[2 * nt], bl[2 * nt + 1]); // hi*lo
                    mma_bf16(cfr[mt][nt], al[mt], bh[2 * nt], bh[2 * nt + 1]); // lo*hi
                }
        }

        // Group barrier: all group warps done reading buffer -> safe to refill
        asm volatile("bar.sync %0, 128;" :: "r"(barid) : "memory");

        // ---- Issue next chunk's staging; it retires behind the scatter ----
        if (i < 7) {
            #pragma unroll
            for (int it = 0; it < 13; it++) {
                int orig = __ldg(g_p2 + (cc + 1) * C2B + brow[it]);
                cp16(Bs + brow[it] * LDB + bj[it] * 16,
                     baseB + (size_t)orig * SPROW + bj[it] * 16);
            }
            asm volatile("cp.async.commit_group;" ::: "memory");
        }

        // ---- Scatter with sign weights (bins clustered by sort) ----
        #pragma unroll
        for (int nt = 0; nt < 2; nt++) {
            int cb = cc * C2B + wn * 16 + nt * 8 + 2 * tg;
            int   h2a = __ldg(g_h2s + cb),  h2b = __ldg(g_h2s + cb + 1);
            float s2a = __ldg(g_s2s + cb),  s2b = __ldg(g_s2s + cb + 1);
            #pragma unroll
            for (int mt = 0; mt < 2; mt++) {
                atomicAdd(outb + ((h1r[mt][0] + h2a) & DMASK),
                          cfr[mt][nt][0] * (s1r[mt][0] * s2a));
                atomicAdd(outb + ((h1r[mt][0] + h2b) & DMASK),
                          cfr[mt][nt][1] * (s1r[mt][0] * s2b));
                atomicAdd(outb + ((h1r[mt][1] + h2a) & DMASK),
                          cfr[mt][nt][2] * (s1r[mt][1] * s2a));
                atomicAdd(outb + ((h1r[mt][1] + h2b) & DMASK),
                          cfr[mt][nt][3] * (s1r[mt][1] * s2b));
            }
        }

        if (i < 7) {
            asm volatile("cp.async.wait_group 0;" ::: "memory");
            asm volatile("bar.sync %0, 128;" :: "r"(barid) : "memory");
        }
    }
}

// ---------------------------------------------------------------------------
// Harness entry
// Inputs: bottom1 [32,512,14,14] f32, bottom2 [32,512,14,14] f32,
//         S1 [512,8192] f32, S2 [512,8192] f32.  Output: [32, 8192] f32
// ---------------------------------------------------------------------------
extern "C" void kernel_launch(void* const* d_in, const int* in_sizes, int n_in,
                              void* d_out, int out_size) {
    const float* b1 = (const float*)d_in[0];
    const float* b2 = (const float*)d_in[1];
    const float* S1 = (const float*)d_in[2];
    const float* S2 = (const float*)d_in[3];
    float* out = (float*)d_out;

    cudaFuncSetAttribute(cbp_main, cudaFuncAttributeMaxDynamicSharedMemorySize,
                         SMEM_BYTES);

    cbp_prep<<<PREP_BLKS + SPLIT_BLKS, NTHREADS>>>(S1, S2, b1, b2, out);
    cbp_sort<<<2, C>>>();
    cbp_main<<<dim3(C / C1B, BATCH), NTHREADS, SMEM_BYTES>>>(out);
}